// round 2
// baseline (speedup 1.0000x reference)
#include <cuda_runtime.h>

#define B_ 8
#define T_ 2048
#define D_ 1024
#define H_ 64

// Scratch for projected Q (pre-scaled by 1/sqrt(HS)), K, V.  4 MB each.
__device__ float g_Q[B_ * T_ * H_];
__device__ float g_K[B_ * T_ * H_];
__device__ float g_V[B_ * T_ * H_];

// ---------------------------------------------------------------------------
// Kernel 1: fused QKV projection.  grid = (M/64, 3), block = 256.
// Tile: BM=64 x BN=64 (full HS), BK=32.  4x4 microtile per thread.
// Q pre-scaled by 0.125 = 1/sqrt(64) (mask(-inf) is scale-invariant).
// ---------------------------------------------------------------------------
__global__ __launch_bounds__(256) void qkv_proj_kernel(
    const float* __restrict__ x,
    const float* __restrict__ Wq, const float* __restrict__ bq,
    const float* __restrict__ Wk, const float* __restrict__ bk,
    const float* __restrict__ Wv, const float* __restrict__ bv)
{
    __shared__ float xs[64][33];
    __shared__ float ws[32][64];

    const float* W;
    const float* bias;
    float* out;
    float scale;
    if (blockIdx.y == 0)      { W = Wq; bias = bq; out = g_Q; scale = 0.125f; }
    else if (blockIdx.y == 1) { W = Wk; bias = bk; out = g_K; scale = 1.0f;   }
    else                      { W = Wv; bias = bv; out = g_V; scale = 1.0f;   }

    const int tid = threadIdx.x;
    const int tx  = tid & 15;
    const int ty  = tid >> 4;
    const int m0  = blockIdx.x * 64;

    float acc[4][4] = {};

    for (int k0 = 0; k0 < D_; k0 += 32) {
        #pragma unroll
        for (int l = 0; l < 2; l++) {
            int lin = tid * 8 + l * 4;
            int i = lin >> 5, k = lin & 31;
            float4 v = *(const float4*)(x + (size_t)(m0 + i) * D_ + k0 + k);
            xs[i][k + 0] = v.x; xs[i][k + 1] = v.y;
            xs[i][k + 2] = v.z; xs[i][k + 3] = v.w;
        }
        #pragma unroll
        for (int l = 0; l < 2; l++) {
            int lin = tid * 8 + l * 4;
            int kr = lin >> 6, c = lin & 63;
            *(float4*)&ws[kr][c] = *(const float4*)(W + (size_t)(k0 + kr) * H_ + c);
        }
        __syncthreads();

        #pragma unroll
        for (int kk = 0; kk < 32; kk++) {
            float a0 = xs[ty * 4 + 0][kk];
            float a1 = xs[ty * 4 + 1][kk];
            float a2 = xs[ty * 4 + 2][kk];
            float a3 = xs[ty * 4 + 3][kk];
            float4 b4 = *(float4*)&ws[kk][tx * 4];
            acc[0][0] += a0 * b4.x; acc[0][1] += a0 * b4.y; acc[0][2] += a0 * b4.z; acc[0][3] += a0 * b4.w;
            acc[1][0] += a1 * b4.x; acc[1][1] += a1 * b4.y; acc[1][2] += a1 * b4.z; acc[1][3] += a1 * b4.w;
            acc[2][0] += a2 * b4.x; acc[2][1] += a2 * b4.y; acc[2][2] += a2 * b4.z; acc[2][3] += a2 * b4.w;
            acc[3][0] += a3 * b4.x; acc[3][1] += a3 * b4.y; acc[3][2] += a3 * b4.z; acc[3][3] += a3 * b4.w;
        }
        __syncthreads();
    }

    #pragma unroll
    for (int i = 0; i < 4; i++) {
        #pragma unroll
        for (int j = 0; j < 4; j++) {
            float bb = bias[tx * 4 + j];
            out[(size_t)(m0 + ty * 4 + i) * H_ + tx * 4 + j] = (acc[i][j] + bb) * scale;
        }
    }
}

// ---------------------------------------------------------------------------
// Kernel 2: causal flash attention, fp32, 4 threads per q-row.
// grid = (32, 8) with qblk = 31 - bx (heavy blocks launch first -> LPT
// scheduling over the causal work imbalance).  block = 256 threads =
// 64 rows x 4 lane-quartet.  Each thread owns a 16-dim slice of q and o;
// QK partials reduced across the quartet with shfl.bfly.
// ---------------------------------------------------------------------------
__global__ __launch_bounds__(256) void attn_kernel(float* __restrict__ out)
{
    __shared__ float Ks[64][64];
    __shared__ float Vs[64][64];

    const int tid  = threadIdx.x;
    const int r    = tid >> 2;          // q-row within tile: 0..63
    const int q4   = tid & 3;           // dim-slice: 0..3 (16 dims each)
    const int qblk = 31 - blockIdx.x;   // heavy first
    const int b    = blockIdx.y;
    const int qrow = qblk * 64 + r;
    const int dbase = q4 * 16;

    // this thread's 16-dim slice of the (pre-scaled) q row
    float q[16];
    {
        const float* Qp = g_Q + ((size_t)b * T_ + qrow) * H_ + dbase;
        #pragma unroll
        for (int i = 0; i < 4; i++) {
            float4 v = *(const float4*)(Qp + i * 4);
            q[i * 4 + 0] = v.x; q[i * 4 + 1] = v.y;
            q[i * 4 + 2] = v.z; q[i * 4 + 3] = v.w;
        }
    }

    float o[16];
    #pragma unroll
    for (int d = 0; d < 16; d++) o[d] = 0.0f;
    float m = -1e30f;
    float l = 0.0f;

    const int ntiles = qblk + 1;
    for (int t = 0; t < ntiles; t++) {
        // cooperative K/V tile load: 4 float4 each per thread, coalesced
        {
            const float* Kt = g_K + ((size_t)b * T_ + t * 64) * H_;
            const float* Vt = g_V + ((size_t)b * T_ + t * 64) * H_;
            float* ksf = &Ks[0][0];
            float* vsf = &Vs[0][0];
            #pragma unroll
            for (int i = 0; i < 4; i++) {
                int lin = i * 1024 + tid * 4;
                *(float4*)(ksf + lin) = *(const float4*)(Kt + lin);
                *(float4*)(vsf + lin) = *(const float4*)(Vt + lin);
            }
        }
        __syncthreads();

        const bool diag = (t == qblk);

        #pragma unroll 1
        for (int c = 0; c < 8; c++) {       // 8 chunks of 8 keys
            float s[8];
            #pragma unroll
            for (int j = 0; j < 8; j++) {
                const float* kp = &Ks[c * 8 + j][dbase];
                float acc = 0.0f;
                #pragma unroll
                for (int i = 0; i < 4; i++) {
                    float4 kv = *(const float4*)(kp + i * 4);
                    acc += q[i * 4 + 0] * kv.x;
                    acc += q[i * 4 + 1] * kv.y;
                    acc += q[i * 4 + 2] * kv.z;
                    acc += q[i * 4 + 3] * kv.w;
                }
                s[j] = acc;
            }
            // reduce partial dots across the 4-lane quartet
            #pragma unroll
            for (int j = 0; j < 8; j++) {
                s[j] += __shfl_xor_sync(0xffffffffu, s[j], 1);
                s[j] += __shfl_xor_sync(0xffffffffu, s[j], 2);
            }
            if (diag) {
                #pragma unroll
                for (int j = 0; j < 8; j++)
                    if (t * 64 + c * 8 + j > qrow) s[j] = -1e30f;
            }
            float mloc = m;
            #pragma unroll
            for (int j = 0; j < 8; j++) mloc = fmaxf(mloc, s[j]);
            float alpha = __expf(m - mloc);
            m = mloc;
            l *= alpha;
            #pragma unroll
            for (int d = 0; d < 16; d++) o[d] *= alpha;
            #pragma unroll
            for (int j = 0; j < 8; j++) {
                float p = __expf(s[j] - m);
                l += p;
                const float* vp = &Vs[c * 8 + j][dbase];
                #pragma unroll
                for (int i = 0; i < 4; i++) {
                    float4 vv = *(const float4*)(vp + i * 4);
                    o[i * 4 + 0] += p * vv.x;
                    o[i * 4 + 1] += p * vv.y;
                    o[i * 4 + 2] += p * vv.z;
                    o[i * 4 + 3] += p * vv.w;
                }
            }
        }
        __syncthreads();
    }

    const float inv_l = 1.0f / l;
    float* op = out + ((size_t)b * T_ + qrow) * H_ + dbase;
    #pragma unroll
    for (int i = 0; i < 4; i++) {
        float4 v;
        v.x = o[i * 4 + 0] * inv_l;
        v.y = o[i * 4 + 1] * inv_l;
        v.z = o[i * 4 + 2] * inv_l;
        v.w = o[i * 4 + 3] * inv_l;
        *(float4*)(op + i * 4) = v;
    }
}

// ---------------------------------------------------------------------------
extern "C" void kernel_launch(void* const* d_in, const int* in_sizes, int n_in,
                              void* d_out, int out_size)
{
    const float* x  = (const float*)d_in[0];
    const float* Wq = (const float*)d_in[1];
    const float* bq = (const float*)d_in[2];
    const float* Wk = (const float*)d_in[3];
    const float* bk = (const float*)d_in[4];
    const float* Wv = (const float*)d_in[5];
    const float* bv = (const float*)d_in[6];
    float* out = (float*)d_out;

    qkv_proj_kernel<<<dim3((B_ * T_) / 64, 3), 256>>>(x, Wq, bq, Wk, bk, Wv, bv);
    attn_kernel<<<dim3(32, 8), 256>>>(out);
}

// round 3
// speedup vs baseline: 3.3411x; 3.3411x over previous
#include <cuda_runtime.h>

#define B_ 8
#define T_ 2048
#define D_ 1024
#define H_ 64

// Scratch for projected Q (pre-scaled by 1/sqrt(HS)), K, V.  4 MB each.
__device__ float g_Q[B_ * T_ * H_];
__device__ float g_K[B_ * T_ * H_];
__device__ float g_V[B_ * T_ * H_];

// Split-KV partials: [b][qblk][split][row][dim] and [b][qblk][split][row][{m,l}]
__device__ float g_Op[B_][32][8][64][H_];   // 33.5 MB, unnormalized o
__device__ float g_Ml[B_][32][8][64][2];    // 1 MB

// ---------------------------------------------------------------------------
// Kernel 1: fused QKV projection.  grid = (M/64, 3), block = 256.
// Tile: BM=64 x BN=64 (full HS), BK=32.  4x4 microtile per thread.
// Q pre-scaled by 0.125 = 1/sqrt(64) (mask(-inf) is scale-invariant).
// ---------------------------------------------------------------------------
__global__ __launch_bounds__(256) void qkv_proj_kernel(
    const float* __restrict__ x,
    const float* __restrict__ Wq, const float* __restrict__ bq,
    const float* __restrict__ Wk, const float* __restrict__ bk,
    const float* __restrict__ Wv, const float* __restrict__ bv)
{
    __shared__ float xs[64][33];
    __shared__ float ws[32][64];

    const float* W;
    const float* bias;
    float* out;
    float scale;
    if (blockIdx.y == 0)      { W = Wq; bias = bq; out = g_Q; scale = 0.125f; }
    else if (blockIdx.y == 1) { W = Wk; bias = bk; out = g_K; scale = 1.0f;   }
    else                      { W = Wv; bias = bv; out = g_V; scale = 1.0f;   }

    const int tid = threadIdx.x;
    const int tx  = tid & 15;
    const int ty  = tid >> 4;
    const int m0  = blockIdx.x * 64;

    float acc[4][4] = {};

    for (int k0 = 0; k0 < D_; k0 += 32) {
        #pragma unroll
        for (int l = 0; l < 2; l++) {
            int lin = tid * 8 + l * 4;
            int i = lin >> 5, k = lin & 31;
            float4 v = *(const float4*)(x + (size_t)(m0 + i) * D_ + k0 + k);
            xs[i][k + 0] = v.x; xs[i][k + 1] = v.y;
            xs[i][k + 2] = v.z; xs[i][k + 3] = v.w;
        }
        #pragma unroll
        for (int l = 0; l < 2; l++) {
            int lin = tid * 8 + l * 4;
            int kr = lin >> 6, c = lin & 63;
            *(float4*)&ws[kr][c] = *(const float4*)(W + (size_t)(k0 + kr) * H_ + c);
        }
        __syncthreads();

        #pragma unroll
        for (int kk = 0; kk < 32; kk++) {
            float a0 = xs[ty * 4 + 0][kk];
            float a1 = xs[ty * 4 + 1][kk];
            float a2 = xs[ty * 4 + 2][kk];
            float a3 = xs[ty * 4 + 3][kk];
            float4 b4 = *(float4*)&ws[kk][tx * 4];
            acc[0][0] += a0 * b4.x; acc[0][1] += a0 * b4.y; acc[0][2] += a0 * b4.z; acc[0][3] += a0 * b4.w;
            acc[1][0] += a1 * b4.x; acc[1][1] += a1 * b4.y; acc[1][2] += a1 * b4.z; acc[1][3] += a1 * b4.w;
            acc[2][0] += a2 * b4.x; acc[2][1] += a2 * b4.y; acc[2][2] += a2 * b4.z; acc[2][3] += a2 * b4.w;
            acc[3][0] += a3 * b4.x; acc[3][1] += a3 * b4.y; acc[3][2] += a3 * b4.z; acc[3][3] += a3 * b4.w;
        }
        __syncthreads();
    }

    #pragma unroll
    for (int i = 0; i < 4; i++) {
        #pragma unroll
        for (int j = 0; j < 4; j++) {
            float bb = bias[tx * 4 + j];
            out[(size_t)(m0 + ty * 4 + i) * H_ + tx * 4 + j] = (acc[i][j] + bb) * scale;
        }
    }
}

// ---------------------------------------------------------------------------
// Kernel 2: split-KV causal flash attention (main pass), fp32.
// One thread per q-row (broadcast smem reads, conflict-free, as in R1).
// Each (b, qblk) has ceil((qblk+1)/4) splits of <=4 KV tiles (64 keys each).
// Flat grid.x = 144 decodes to (qblk, split); heavy groups launch first (LPT).
// Each split writes unnormalized (o, m, l) partials to scratch.
// ---------------------------------------------------------------------------
__global__ __launch_bounds__(64) void attn_split_kernel()
{
    __shared__ float Ks[64][64];
    __shared__ float Vs[64][64];

    const int bxr = 143 - (int)blockIdx.x;   // heavy (large g) first
    const int b   = blockIdx.y;

    // group g: qblks 4g..4g+3, each with g+1 splits; offset(g) = 2g(g+1)
    int g = 0;
    #pragma unroll
    for (int h = 1; h < 8; h++)
        if (bxr >= 2 * h * (h + 1)) g = h;
    const int rem = bxr - 2 * g * (g + 1);
    const int qi  = rem / (g + 1);
    const int s   = rem - qi * (g + 1);
    const int t   = 4 * g + qi;              // q-block index 0..31

    const int r    = threadIdx.x;            // q-row within tile
    const int qrow = t * 64 + r;

    // load this thread's (pre-scaled) q row into registers
    float q[64];
    {
        const float* Qrow = g_Q + ((size_t)b * T_ + qrow) * H_;
        #pragma unroll
        for (int d4 = 0; d4 < 16; d4++) {
            float4 v = *(const float4*)(Qrow + d4 * 4);
            q[d4 * 4 + 0] = v.x; q[d4 * 4 + 1] = v.y;
            q[d4 * 4 + 2] = v.z; q[d4 * 4 + 3] = v.w;
        }
    }

    float o[64];
    #pragma unroll
    for (int d = 0; d < 64; d++) o[d] = 0.0f;
    float m = -1e30f;
    float l = 0.0f;

    const int t0 = s * 4;
    const int t1 = min(s * 4 + 4, t + 1);

    for (int tt = t0; tt < t1; tt++) {
        // cooperatively load K/V tile (64 keys x 64 dims), coalesced
        {
            const float* Kt = g_K + ((size_t)b * T_ + tt * 64) * H_;
            const float* Vt = g_V + ((size_t)b * T_ + tt * 64) * H_;
            float* ksf = &Ks[0][0];
            float* vsf = &Vs[0][0];
            #pragma unroll
            for (int l2 = 0; l2 < 16; l2++) {
                int lin = l2 * 256 + r * 4;
                *(float4*)(ksf + lin) = *(const float4*)(Kt + lin);
                *(float4*)(vsf + lin) = *(const float4*)(Vt + lin);
            }
        }
        __syncthreads();

        const bool diag = (tt == t);

        #pragma unroll 1
        for (int c = 0; c < 8; c++) {          // 8 chunks of 8 keys
            float sc[8];
            #pragma unroll
            for (int j = 0; j < 8; j++) {
                float acc = 0.0f;
                #pragma unroll
                for (int d4 = 0; d4 < 16; d4++) {
                    float4 kv = *(const float4*)&Ks[c * 8 + j][d4 * 4];
                    acc += q[d4 * 4 + 0] * kv.x;
                    acc += q[d4 * 4 + 1] * kv.y;
                    acc += q[d4 * 4 + 2] * kv.z;
                    acc += q[d4 * 4 + 3] * kv.w;
                }
                sc[j] = acc;
            }
            if (diag) {
                #pragma unroll
                for (int j = 0; j < 8; j++)
                    if (tt * 64 + c * 8 + j > qrow) sc[j] = -1e30f;
            }
            float mloc = m;
            #pragma unroll
            for (int j = 0; j < 8; j++) mloc = fmaxf(mloc, sc[j]);
            float alpha = __expf(m - mloc);
            m = mloc;
            l *= alpha;
            #pragma unroll
            for (int d = 0; d < 64; d++) o[d] *= alpha;
            #pragma unroll
            for (int j = 0; j < 8; j++) {
                float p = __expf(sc[j] - m);
                l += p;
                #pragma unroll
                for (int d4 = 0; d4 < 16; d4++) {
                    float4 vv = *(const float4*)&Vs[c * 8 + j][d4 * 4];
                    o[d4 * 4 + 0] += p * vv.x;
                    o[d4 * 4 + 1] += p * vv.y;
                    o[d4 * 4 + 2] += p * vv.z;
                    o[d4 * 4 + 3] += p * vv.w;
                }
            }
        }
        __syncthreads();
    }

    // write unnormalized partials
    {
        float* op = &g_Op[b][t][s][r][0];
        #pragma unroll
        for (int d4 = 0; d4 < 16; d4++) {
            float4 v;
            v.x = o[d4 * 4 + 0]; v.y = o[d4 * 4 + 1];
            v.z = o[d4 * 4 + 2]; v.w = o[d4 * 4 + 3];
            *(float4*)(op + d4 * 4) = v;
        }
        g_Ml[b][t][s][r][0] = m;
        g_Ml[b][t][s][r][1] = l;
    }
}

// ---------------------------------------------------------------------------
// Kernel 3: combine split partials.  grid = (32, 8), block = 256.
// Thread = (row r = tid/4, 16-dim slice q4 = tid%4).
// ---------------------------------------------------------------------------
__global__ __launch_bounds__(256) void attn_combine_kernel(float* __restrict__ out)
{
    const int t   = blockIdx.x;
    const int b   = blockIdx.y;
    const int tid = threadIdx.x;
    const int r   = tid >> 2;
    const int q4  = tid & 3;
    const int dbase = q4 * 16;
    const int ns  = t / 4 + 1;

    float mv[8], lv[8], w[8];
    float M = -1e30f;
    for (int i = 0; i < ns; i++) {
        mv[i] = g_Ml[b][t][i][r][0];
        lv[i] = g_Ml[b][t][i][r][1];
        M = fmaxf(M, mv[i]);
    }
    float L = 0.0f;
    for (int i = 0; i < ns; i++) {
        w[i] = __expf(mv[i] - M);
        L += w[i] * lv[i];
    }
    const float invL = 1.0f / L;

    float acc[16];
    #pragma unroll
    for (int d = 0; d < 16; d++) acc[d] = 0.0f;

    for (int i = 0; i < ns; i++) {
        const float* op = &g_Op[b][t][i][r][dbase];
        const float wi = w[i];
        #pragma unroll
        for (int d4 = 0; d4 < 4; d4++) {
            float4 v = *(const float4*)(op + d4 * 4);
            acc[d4 * 4 + 0] += wi * v.x;
            acc[d4 * 4 + 1] += wi * v.y;
            acc[d4 * 4 + 2] += wi * v.z;
            acc[d4 * 4 + 3] += wi * v.w;
        }
    }

    float* orow = out + ((size_t)b * T_ + t * 64 + r) * H_ + dbase;
    #pragma unroll
    for (int d4 = 0; d4 < 4; d4++) {
        float4 v;
        v.x = acc[d4 * 4 + 0] * invL;
        v.y = acc[d4 * 4 + 1] * invL;
        v.z = acc[d4 * 4 + 2] * invL;
        v.w = acc[d4 * 4 + 3] * invL;
        *(float4*)(orow + d4 * 4) = v;
    }
}

// ---------------------------------------------------------------------------
extern "C" void kernel_launch(void* const* d_in, const int* in_sizes, int n_in,
                              void* d_out, int out_size)
{
    const float* x  = (const float*)d_in[0];
    const float* Wq = (const float*)d_in[1];
    const float* bq = (const float*)d_in[2];
    const float* Wk = (const float*)d_in[3];
    const float* bk = (const float*)d_in[4];
    const float* Wv = (const float*)d_in[5];
    const float* bv = (const float*)d_in[6];
    float* out = (float*)d_out;

    qkv_proj_kernel<<<dim3((B_ * T_) / 64, 3), 256>>>(x, Wq, bq, Wk, bk, Wv, bv);
    attn_split_kernel<<<dim3(144, B_), 64>>>();
    attn_combine_kernel<<<dim3(32, B_), 256>>>(out);
}

// round 5
// speedup vs baseline: 5.0765x; 1.5194x over previous
#include <cuda_runtime.h>
#include <cstdint>

#define B_ 8
#define T_ 2048
#define D_ 1024
#define H_ 64
#define M_ (B_ * T_)        // 16384 rows

// ---------------------------------------------------------------------------
// Device scratch
// ---------------------------------------------------------------------------
__device__ float g_Q[M_ * H_];
__device__ float g_K[M_ * H_];
__device__ float g_V[M_ * H_];

// W transposed, bf16 hi/lo split, packed 2-per-u32 along k:
// [j][n][kpair], j = 0..2 hi(Q,K,V), 3..5 lo(Q,K,V).  786 KB.
__device__ uint32_t g_Whl[6][64][512];

// Split-KV partials
__device__ float g_Op[B_][32][8][64][H_];
__device__ float g_Ml[B_][32][8][64][2];

// ---------------------------------------------------------------------------
// Helpers
// ---------------------------------------------------------------------------
__device__ __forceinline__ uint32_t smem_u32(const void* p) {
    uint32_t a;
    asm("{ .reg .u64 t; cvta.to.shared.u64 t, %1; cvt.u32.u64 %0, t; }" : "=r"(a) : "l"(p));
    return a;
}
// pack: lo element -> bits [0:16), hi element -> bits [16:32)
__device__ __forceinline__ uint32_t packbf(float elo, float ehi) {
    uint32_t r;
    asm("cvt.rn.bf16x2.f32 %0, %1, %2;" : "=r"(r) : "f"(ehi), "f"(elo));
    return r;
}
__device__ __forceinline__ void mma_bf16(float* c,
    uint32_t a0, uint32_t a1, uint32_t a2, uint32_t a3, uint32_t b0, uint32_t b1)
{
    asm volatile("mma.sync.aligned.m16n8k16.row.col.f32.bf16.bf16.f32 "
        "{%0,%1,%2,%3}, {%4,%5,%6,%7}, {%8,%9}, {%0,%1,%2,%3};"
        : "+f"(c[0]), "+f"(c[1]), "+f"(c[2]), "+f"(c[3])
        : "r"(a0), "r"(a1), "r"(a2), "r"(a3), "r"(b0), "r"(b1));
}
__device__ __forceinline__ void cp_async16(uint32_t dst, const void* src) {
    asm volatile("cp.async.cg.shared.global [%0], [%1], 16;" :: "r"(dst), "l"(src) : "memory");
}
#define CP_COMMIT()  asm volatile("cp.async.commit_group;" ::: "memory")
#define CP_WAIT1()   asm volatile("cp.async.wait_group 1;"  ::: "memory")

// ---------------------------------------------------------------------------
// Kernel 0: transpose + bf16 hi/lo split + pack of the three weight matrices.
// One thread per (o, n, kpair).
// ---------------------------------------------------------------------------
__global__ __launch_bounds__(256) void wsplit_kernel(
    const float* __restrict__ Wq, const float* __restrict__ Wk, const float* __restrict__ Wv)
{
    int idx = blockIdx.x * 256 + threadIdx.x;   // 0 .. 3*64*512-1
    int o  = idx >> 15;                         // 0..2
    int n  = (idx >> 9) & 63;
    int kp = idx & 511;
    const float* W = (o == 0) ? Wq : (o == 1) ? Wk : Wv;
    float w0 = W[(2 * kp + 0) * 64 + n];
    float w1 = W[(2 * kp + 1) * 64 + n];
    uint32_t hp = packbf(w0, w1);
    float h0 = __uint_as_float(hp << 16);
    float h1 = __uint_as_float(hp & 0xffff0000u);
    uint32_t lp = packbf(w0 - h0, w1 - h1);
    g_Whl[o][n][kp]     = hp;
    g_Whl[3 + o][n][kp] = lp;
}

// ---------------------------------------------------------------------------
// Kernel 1: fused QKV projection via mma.sync bf16 (3-term split).
// grid = 128, block = 256 (8 warps x 16 rows).  CTA tile: M=128, N=64, 3 outs.
// k-chunk 32 (16 bf16-pairs), 2-stage smem ring; W via cp.async, x split
// in-kernel with register prefetch.  Q written pre-scaled by 0.125.
//
// Stage layout (u32 units, pair-stride padded to 20 for conflict-free frags):
//   [0,2560)        xs_hi  [128 rows][20]
//   [2560,5120)     xs_lo
//   [5120,12800)    ws     [6 j][64 n][20]
// ---------------------------------------------------------------------------
#define STAGE_U   12800
#define SMEM_DYN  (2 * STAGE_U * 4)

__global__ __launch_bounds__(256, 1) void qkv_mma_kernel(
    const float* __restrict__ x,
    const float* __restrict__ bq, const float* __restrict__ bk, const float* __restrict__ bv)
{
    extern __shared__ uint32_t sm[];
    __shared__ float sbias[3][64];

    const int tid  = threadIdx.x;
    const int w    = tid >> 5;
    const int lane = tid & 31;
    const int gid  = lane >> 2;      // 0..7
    const int tg   = lane & 3;       // 0..3
    const int m0   = blockIdx.x * 128;

    if (tid < 64) {
        sbias[0][tid] = bq[tid];
        sbias[1][tid] = bk[tid];
        sbias[2][tid] = bv[tid];
    }

    // x prefetch addressing: thread -> (row, half)
    const int xrow  = tid >> 1;
    const int xhalf = tid & 1;
    const float* xbase = x + (size_t)(m0 + xrow) * D_ + xhalf * 16;

    // W cp.async addressing: 6 segments of 16B per thread per chunk
    // seg id = it*256 + tid -> j = sid>>8, n = (sid>>2)&63, g = sid&3
    uint32_t wdst[6];
    const uint32_t* wsrc[6];
    #pragma unroll
    for (int it = 0; it < 6; it++) {
        int sid = it * 256 + tid;
        int j = sid >> 8, n = (sid >> 2) & 63, g = sid & 3;
        wdst[it] = 5120u + (uint32_t)j * 1280u + (uint32_t)n * 20u + (uint32_t)g * 4u;
        wsrc[it] = &g_Whl[j][n][g * 4];
    }
    const uint32_t smbase = smem_u32(sm);

    // accumulators [out][ntile][4]
    float acc[3][8][4];
    #pragma unroll
    for (int o = 0; o < 3; o++)
        #pragma unroll
        for (int nt = 0; nt < 8; nt++)
            #pragma unroll
            for (int i = 0; i < 4; i++) acc[o][nt][i] = 0.0f;

    // prologue: W chunk 0 -> stage 0;  x chunk 0 -> regs
    #pragma unroll
    for (int it = 0; it < 6; it++)
        cp_async16(smbase + wdst[it] * 4, wsrc[it]);
    CP_COMMIT();

    float4 xv[2][4];
    #pragma unroll
    for (int i = 0; i < 4; i++) xv[0][i] = *(const float4*)(xbase + i * 4);

    #pragma unroll 2
    for (int s = 0; s < 32; s++) {
        const int p   = s & 1;
        const int np  = p ^ 1;
        const uint32_t st = (uint32_t)p * STAGE_U;

        // issue next chunk's W cp.async + x LDG
        if (s + 1 < 32) {
            #pragma unroll
            for (int it = 0; it < 6; it++)
                cp_async16(smbase + (np * STAGE_U + wdst[it]) * 4,
                           wsrc[it] + (size_t)(s + 1) * 16);
        }
        CP_COMMIT();
        if (s + 1 < 32) {
            const float* xp = xbase + (s + 1) * 32;
            #pragma unroll
            for (int i = 0; i < 4; i++) xv[np][i] = *(const float4*)(xp + i * 4);
        }

        // split + STS x chunk s (this thread: 16 floats = 8 pairs)
        {
            uint32_t hp[8], lp[8];
            #pragma unroll
            for (int i = 0; i < 4; i++) {
                float4 v = xv[p][i];
                uint32_t h01 = packbf(v.x, v.y);
                uint32_t h23 = packbf(v.z, v.w);
                float r0 = v.x - __uint_as_float(h01 << 16);
                float r1 = v.y - __uint_as_float(h01 & 0xffff0000u);
                float r2 = v.z - __uint_as_float(h23 << 16);
                float r3 = v.w - __uint_as_float(h23 & 0xffff0000u);
                hp[i * 2 + 0] = h01; hp[i * 2 + 1] = h23;
                lp[i * 2 + 0] = packbf(r0, r1);
                lp[i * 2 + 1] = packbf(r2, r3);
            }
            uint32_t* xhi = &sm[st + (uint32_t)xrow * 20u + (uint32_t)xhalf * 8u];
            uint32_t* xlo = xhi + 2560;
            *(uint4*)(xhi + 0) = make_uint4(hp[0], hp[1], hp[2], hp[3]);
            *(uint4*)(xhi + 4) = make_uint4(hp[4], hp[5], hp[6], hp[7]);
            *(uint4*)(xlo + 0) = make_uint4(lp[0], lp[1], lp[2], lp[3]);
            *(uint4*)(xlo + 4) = make_uint4(lp[4], lp[5], lp[6], lp[7]);
        }

        CP_WAIT1();
        __syncthreads();

        // mma over stage p: 2 k-steps x 3 outs x 8 ntiles x 3 products
        const uint32_t arow = st + (uint32_t)(w * 16 + gid) * 20u;
        #pragma unroll
        for (int kk = 0; kk < 2; kk++) {
            const uint32_t ka = arow + kk * 8 + tg;
            uint32_t ah0 = sm[ka];
            uint32_t ah1 = sm[ka + 8 * 20];
            uint32_t ah2 = sm[ka + 4];
            uint32_t ah3 = sm[ka + 8 * 20 + 4];
            uint32_t al0 = sm[ka + 2560];
            uint32_t al1 = sm[ka + 2560 + 8 * 20];
            uint32_t al2 = sm[ka + 2560 + 4];
            uint32_t al3 = sm[ka + 2560 + 8 * 20 + 4];
            #pragma unroll
            for (int o = 0; o < 3; o++) {
                #pragma unroll
                for (int nt = 0; nt < 8; nt++) {
                    const uint32_t kb = st + 5120u + (uint32_t)o * 1280u
                                      + (uint32_t)(nt * 8 + gid) * 20u + kk * 8 + tg;
                    uint32_t bh0 = sm[kb];
                    uint32_t bh1 = sm[kb + 4];
                    uint32_t bl0 = sm[kb + 3 * 1280];
                    uint32_t bl1 = sm[kb + 3 * 1280 + 4];
                    mma_bf16(acc[o][nt], ah0, ah1, ah2, ah3, bh0, bh1);
                    mma_bf16(acc[o][nt], ah0, ah1, ah2, ah3, bl0, bl1);
                    mma_bf16(acc[o][nt], al0, al1, al2, al3, bh0, bh1);
                }
            }
        }
        __syncthreads();
    }

    // epilogue: bias + scale, write fp32
    const int r0 = m0 + w * 16 + gid;
    #pragma unroll
    for (int o = 0; o < 3; o++) {
        const float scale = (o == 0) ? 0.125f : 1.0f;
        float* outb = (o == 0) ? g_Q : (o == 1) ? g_K : g_V;
        #pragma unroll
        for (int nt = 0; nt < 8; nt++) {
            const int col = nt * 8 + 2 * tg;
            const float b0v = sbias[o][col], b1v = sbias[o][col + 1];
            float2 v0, v1;
            v0.x = (acc[o][nt][0] + b0v) * scale;
            v0.y = (acc[o][nt][1] + b1v) * scale;
            v1.x = (acc[o][nt][2] + b0v) * scale;
            v1.y = (acc[o][nt][3] + b1v) * scale;
            *(float2*)(outb + (size_t)r0 * H_ + col)       = v0;
            *(float2*)(outb + (size_t)(r0 + 8) * H_ + col) = v1;
        }
    }
}

// ---------------------------------------------------------------------------
// Kernel 2: split-KV causal flash attention (main pass), fp32.  (R3, unchanged)
// ---------------------------------------------------------------------------
__global__ __launch_bounds__(64) void attn_split_kernel()
{
    __shared__ float Ks[64][64];
    __shared__ float Vs[64][64];

    const int bxr = 143 - (int)blockIdx.x;
    const int b   = blockIdx.y;

    int g = 0;
    #pragma unroll
    for (int h = 1; h < 8; h++)
        if (bxr >= 2 * h * (h + 1)) g = h;
    const int rem = bxr - 2 * g * (g + 1);
    const int qi  = rem / (g + 1);
    const int s   = rem - qi * (g + 1);
    const int t   = 4 * g + qi;

    const int r    = threadIdx.x;
    const int qrow = t * 64 + r;

    float q[64];
    {
        const float* Qrow = g_Q + ((size_t)b * T_ + qrow) * H_;
        #pragma unroll
        for (int d4 = 0; d4 < 16; d4++) {
            float4 v = *(const float4*)(Qrow + d4 * 4);
            q[d4 * 4 + 0] = v.x; q[d4 * 4 + 1] = v.y;
            q[d4 * 4 + 2] = v.z; q[d4 * 4 + 3] = v.w;
        }
    }

    float o[64];
    #pragma unroll
    for (int d = 0; d < 64; d++) o[d] = 0.0f;
    float m = -1e30f;
    float l = 0.0f;

    const int t0 = s * 4;
    const int t1 = min(s * 4 + 4, t + 1);

    for (int tt = t0; tt < t1; tt++) {
        {
            const float* Kt = g_K + ((size_t)b * T_ + tt * 64) * H_;
            const float* Vt = g_V + ((size_t)b * T_ + tt * 64) * H_;
            float* ksf = &Ks[0][0];
            float* vsf = &Vs[0][0];
            #pragma unroll
            for (int l2 = 0; l2 < 16; l2++) {
                int lin = l2 * 256 + r * 4;
                *(float4*)(ksf + lin) = *(const float4*)(Kt + lin);
                *(float4*)(vsf + lin) = *(const float4*)(Vt + lin);
            }
        }
        __syncthreads();

        const bool diag = (tt == t);

        #pragma unroll 1
        for (int c = 0; c < 8; c++) {
            float sc[8];
            #pragma unroll
            for (int j = 0; j < 8; j++) {
                float acc = 0.0f;
                #pragma unroll
                for (int d4 = 0; d4 < 16; d4++) {
                    float4 kv = *(const float4*)&Ks[c * 8 + j][d4 * 4];
                    acc += q[d4 * 4 + 0] * kv.x;
                    acc += q[d4 * 4 + 1] * kv.y;
                    acc += q[d4 * 4 + 2] * kv.z;
                    acc += q[d4 * 4 + 3] * kv.w;
                }
                sc[j] = acc;
            }
            if (diag) {
                #pragma unroll
                for (int j = 0; j < 8; j++)
                    if (tt * 64 + c * 8 + j > qrow) sc[j] = -1e30f;
            }
            float mloc = m;
            #pragma unroll
            for (int j = 0; j < 8; j++) mloc = fmaxf(mloc, sc[j]);
            float alpha = __expf(m - mloc);
            m = mloc;
            l *= alpha;
            #pragma unroll
            for (int d = 0; d < 64; d++) o[d] *= alpha;
            #pragma unroll
            for (int j = 0; j < 8; j++) {
                float p = __expf(sc[j] - m);
                l += p;
                #pragma unroll
                for (int d4 = 0; d4 < 16; d4++) {
                    float4 vv = *(const float4*)&Vs[c * 8 + j][d4 * 4];
                    o[d4 * 4 + 0] += p * vv.x;
                    o[d4 * 4 + 1] += p * vv.y;
                    o[d4 * 4 + 2] += p * vv.z;
                    o[d4 * 4 + 3] += p * vv.w;
                }
            }
        }
        __syncthreads();
    }

    {
        float* op = &g_Op[b][t][s][r][0];
        #pragma unroll
        for (int d4 = 0; d4 < 16; d4++) {
            float4 v;
            v.x = o[d4 * 4 + 0]; v.y = o[d4 * 4 + 1];
            v.z = o[d4 * 4 + 2]; v.w = o[d4 * 4 + 3];
            *(float4*)(op + d4 * 4) = v;
        }
        g_Ml[b][t][s][r][0] = m;
        g_Ml[b][t][s][r][1] = l;
    }
}

// ---------------------------------------------------------------------------
// Kernel 3: combine split partials.  (R3, unchanged)
// ---------------------------------------------------------------------------
__global__ __launch_bounds__(256) void attn_combine_kernel(float* __restrict__ out)
{
    const int t   = blockIdx.x;
    const int b   = blockIdx.y;
    const int tid = threadIdx.x;
    const int r   = tid >> 2;
    const int q4  = tid & 3;
    const int dbase = q4 * 16;
    const int ns  = t / 4 + 1;

    float mv[8], lv[8], w[8];
    float M = -1e30f;
    for (int i = 0; i < ns; i++) {
        mv[i] = g_Ml[b][t][i][r][0];
        lv[i] = g_Ml[b][t][i][r][1];
        M = fmaxf(M, mv[i]);
    }
    float L = 0.0f;
    for (int i = 0; i < ns; i++) {
        w[i] = __expf(mv[i] - M);
        L += w[i] * lv[i];
    }
    const float invL = 1.0f / L;

    float acc[16];
    #pragma unroll
    for (int d = 0; d < 16; d++) acc[d] = 0.0f;

    for (int i = 0; i < ns; i++) {
        const float* op = &g_Op[b][t][i][r][dbase];
        const float wi = w[i];
        #pragma unroll
        for (int d4 = 0; d4 < 4; d4++) {
            float4 v = *(const float4*)(op + d4 * 4);
            acc[d4 * 4 + 0] += wi * v.x;
            acc[d4 * 4 + 1] += wi * v.y;
            acc[d4 * 4 + 2] += wi * v.z;
            acc[d4 * 4 + 3] += wi * v.w;
        }
    }

    float* orow = out + ((size_t)b * T_ + t * 64 + r) * H_ + dbase;
    #pragma unroll
    for (int d4 = 0; d4 < 4; d4++) {
        float4 v;
        v.x = acc[d4 * 4 + 0] * invL;
        v.y = acc[d4 * 4 + 1] * invL;
        v.z = acc[d4 * 4 + 2] * invL;
        v.w = acc[d4 * 4 + 3] * invL;
        *(float4*)(orow + d4 * 4) = v;
    }
}

// ---------------------------------------------------------------------------
extern "C" void kernel_launch(void* const* d_in, const int* in_sizes, int n_in,
                              void* d_out, int out_size)
{
    const float* x  = (const float*)d_in[0];
    const float* Wq = (const float*)d_in[1];
    const float* bq = (const float*)d_in[2];
    const float* Wk = (const float*)d_in[3];
    const float* bk = (const float*)d_in[4];
    const float* Wv = (const float*)d_in[5];
    const float* bv = (const float*)d_in[6];
    float* out = (float*)d_out;

    cudaFuncSetAttribute(qkv_mma_kernel,
                         cudaFuncAttributeMaxDynamicSharedMemorySize, SMEM_DYN);

    wsplit_kernel<<<384, 256>>>(Wq, Wk, Wv);
    qkv_mma_kernel<<<128, 256, SMEM_DYN>>>(x, bq, bk, bv);
    attn_split_kernel<<<dim3(144, B_), 64>>>();
    attn_combine_kernel<<<dim3(32, B_), 256>>>(out);
}

// round 7
// speedup vs baseline: 8.1901x; 1.6133x over previous
#include <cuda_runtime.h>
#include <cstdint>

#define B_ 8
#define T_ 2048
#define D_ 1024
#define H_ 64
#define M_ (B_ * T_)        // 16384 rows

// ---------------------------------------------------------------------------
// Device scratch
// ---------------------------------------------------------------------------
__device__ float g_V[M_ * H_];                      // fp32 V (for transpose+split)
__device__ uint32_t g_Qh[M_ * 32], g_Ql[M_ * 32];   // packed bf16 hi/lo Q (pre-scaled)
__device__ uint32_t g_Kh[M_ * 32], g_Kl[M_ * 32];   // packed bf16 hi/lo K

// W transposed, bf16 hi/lo split, packed 2-per-u32 along k
__device__ uint32_t g_Whl[6][64][512];

// Split-KV partials
__device__ float g_Op[B_][32][8][64][H_];
__device__ float g_Ml[B_][32][8][64][2];

// ---------------------------------------------------------------------------
// Helpers
// ---------------------------------------------------------------------------
__device__ __forceinline__ uint32_t smem_u32(const void* p) {
    uint32_t a;
    asm("{ .reg .u64 t; cvta.to.shared.u64 t, %1; cvt.u32.u64 %0, t; }" : "=r"(a) : "l"(p));
    return a;
}
// pack: elo -> bits [0:16), ehi -> bits [16:32)
__device__ __forceinline__ uint32_t packbf(float elo, float ehi) {
    uint32_t r;
    asm("cvt.rn.bf16x2.f32 %0, %1, %2;" : "=r"(r) : "f"(ehi), "f"(elo));
    return r;
}
__device__ __forceinline__ float bflo(uint32_t p) { return __uint_as_float(p << 16); }
__device__ __forceinline__ float bfhi(uint32_t p) { return __uint_as_float(p & 0xffff0000u); }

__device__ __forceinline__ void mma_bf16(float* c,
    uint32_t a0, uint32_t a1, uint32_t a2, uint32_t a3, uint32_t b0, uint32_t b1)
{
    asm volatile("mma.sync.aligned.m16n8k16.row.col.f32.bf16.bf16.f32 "
        "{%0,%1,%2,%3}, {%4,%5,%6,%7}, {%8,%9}, {%0,%1,%2,%3};"
        : "+f"(c[0]), "+f"(c[1]), "+f"(c[2]), "+f"(c[3])
        : "r"(a0), "r"(a1), "r"(a2), "r"(a3), "r"(b0), "r"(b1));
}
__device__ __forceinline__ void cp_async16(uint32_t dst, const void* src) {
    asm volatile("cp.async.cg.shared.global [%0], [%1], 16;" :: "r"(dst), "l"(src) : "memory");
}
#define CP_COMMIT()  asm volatile("cp.async.commit_group;" ::: "memory")
#define CP_WAIT1()   asm volatile("cp.async.wait_group 1;"  ::: "memory")
#define CP_WAIT0()   asm volatile("cp.async.wait_group 0;"  ::: "memory")

// ---------------------------------------------------------------------------
// Kernel 0: transpose + bf16 hi/lo split + pack of the three weight matrices.
// ---------------------------------------------------------------------------
__global__ __launch_bounds__(256) void wsplit_kernel(
    const float* __restrict__ Wq, const float* __restrict__ Wk, const float* __restrict__ Wv)
{
    int idx = blockIdx.x * 256 + threadIdx.x;
    int o  = idx >> 15;
    int n  = (idx >> 9) & 63;
    int kp = idx & 511;
    const float* W = (o == 0) ? Wq : (o == 1) ? Wk : Wv;
    float w0 = W[(2 * kp + 0) * 64 + n];
    float w1 = W[(2 * kp + 1) * 64 + n];
    uint32_t hp = packbf(w0, w1);
    uint32_t lp = packbf(w0 - bflo(hp), w1 - bfhi(hp));
    g_Whl[o][n][kp]     = hp;
    g_Whl[3 + o][n][kp] = lp;
}

// ---------------------------------------------------------------------------
// Kernel 1: fused QKV projection via mma.sync bf16 (3-term split).
// Epilogue writes Q,K as packed bf16 hi/lo (fragment-ready) and V as fp32.
// ---------------------------------------------------------------------------
#define STAGE_U   12800
#define SMEM_DYN  (2 * STAGE_U * 4)

__global__ __launch_bounds__(256, 1) void qkv_mma_kernel(
    const float* __restrict__ x,
    const float* __restrict__ bq, const float* __restrict__ bk, const float* __restrict__ bv)
{
    extern __shared__ uint32_t sm[];
    __shared__ float sbias[3][64];

    const int tid  = threadIdx.x;
    const int w    = tid >> 5;
    const int lane = tid & 31;
    const int gid  = lane >> 2;
    const int tg   = lane & 3;
    const int m0   = blockIdx.x * 128;

    if (tid < 64) {
        sbias[0][tid] = bq[tid];
        sbias[1][tid] = bk[tid];
        sbias[2][tid] = bv[tid];
    }

    const int xrow  = tid >> 1;
    const int xhalf = tid & 1;
    const float* xbase = x + (size_t)(m0 + xrow) * D_ + xhalf * 16;

    uint32_t wdst[6];
    const uint32_t* wsrc[6];
    #pragma unroll
    for (int it = 0; it < 6; it++) {
        int sid = it * 256 + tid;
        int j = sid >> 8, n = (sid >> 2) & 63, g = sid & 3;
        wdst[it] = 5120u + (uint32_t)j * 1280u + (uint32_t)n * 20u + (uint32_t)g * 4u;
        wsrc[it] = &g_Whl[j][n][g * 4];
    }
    const uint32_t smbase = smem_u32(sm);

    float acc[3][8][4];
    #pragma unroll
    for (int o = 0; o < 3; o++)
        #pragma unroll
        for (int nt = 0; nt < 8; nt++)
            #pragma unroll
            for (int i = 0; i < 4; i++) acc[o][nt][i] = 0.0f;

    #pragma unroll
    for (int it = 0; it < 6; it++)
        cp_async16(smbase + wdst[it] * 4, wsrc[it]);
    CP_COMMIT();

    float4 xv[2][4];
    #pragma unroll
    for (int i = 0; i < 4; i++) xv[0][i] = *(const float4*)(xbase + i * 4);

    #pragma unroll 2
    for (int s = 0; s < 32; s++) {
        const int p   = s & 1;
        const int np  = p ^ 1;
        const uint32_t st = (uint32_t)p * STAGE_U;

        if (s + 1 < 32) {
            #pragma unroll
            for (int it = 0; it < 6; it++)
                cp_async16(smbase + (np * STAGE_U + wdst[it]) * 4,
                           wsrc[it] + (size_t)(s + 1) * 16);
        }
        CP_COMMIT();
        if (s + 1 < 32) {
            const float* xp = xbase + (s + 1) * 32;
            #pragma unroll
            for (int i = 0; i < 4; i++) xv[np][i] = *(const float4*)(xp + i * 4);
        }

        {
            uint32_t hp[8], lp[8];
            #pragma unroll
            for (int i = 0; i < 4; i++) {
                float4 v = xv[p][i];
                uint32_t h01 = packbf(v.x, v.y);
                uint32_t h23 = packbf(v.z, v.w);
                hp[i * 2 + 0] = h01; hp[i * 2 + 1] = h23;
                lp[i * 2 + 0] = packbf(v.x - bflo(h01), v.y - bfhi(h01));
                lp[i * 2 + 1] = packbf(v.z - bflo(h23), v.w - bfhi(h23));
            }
            uint32_t* xhi = &sm[st + (uint32_t)xrow * 20u + (uint32_t)xhalf * 8u];
            uint32_t* xlo = xhi + 2560;
            *(uint4*)(xhi + 0) = make_uint4(hp[0], hp[1], hp[2], hp[3]);
            *(uint4*)(xhi + 4) = make_uint4(hp[4], hp[5], hp[6], hp[7]);
            *(uint4*)(xlo + 0) = make_uint4(lp[0], lp[1], lp[2], lp[3]);
            *(uint4*)(xlo + 4) = make_uint4(lp[4], lp[5], lp[6], lp[7]);
        }

        CP_WAIT1();
        __syncthreads();

        const uint32_t arow = st + (uint32_t)(w * 16 + gid) * 20u;
        #pragma unroll
        for (int kk = 0; kk < 2; kk++) {
            const uint32_t ka = arow + kk * 8 + tg;
            uint32_t ah0 = sm[ka];
            uint32_t ah1 = sm[ka + 8 * 20];
            uint32_t ah2 = sm[ka + 4];
            uint32_t ah3 = sm[ka + 8 * 20 + 4];
            uint32_t al0 = sm[ka + 2560];
            uint32_t al1 = sm[ka + 2560 + 8 * 20];
            uint32_t al2 = sm[ka + 2560 + 4];
            uint32_t al3 = sm[ka + 2560 + 8 * 20 + 4];
            #pragma unroll
            for (int o = 0; o < 3; o++) {
                #pragma unroll
                for (int nt = 0; nt < 8; nt++) {
                    const uint32_t kb = st + 5120u + (uint32_t)o * 1280u
                                      + (uint32_t)(nt * 8 + gid) * 20u + kk * 8 + tg;
                    uint32_t bh0 = sm[kb];
                    uint32_t bh1 = sm[kb + 4];
                    uint32_t bl0 = sm[kb + 3 * 1280];
                    uint32_t bl1 = sm[kb + 3 * 1280 + 4];
                    mma_bf16(acc[o][nt], ah0, ah1, ah2, ah3, bh0, bh1);
                    mma_bf16(acc[o][nt], ah0, ah1, ah2, ah3, bl0, bl1);
                    mma_bf16(acc[o][nt], al0, al1, al2, al3, bh0, bh1);
                }
            }
        }
        __syncthreads();
    }

    // epilogue: Q,K -> packed bf16 hi/lo; V -> fp32
    const int r0 = m0 + w * 16 + gid;
    #pragma unroll
    for (int o = 0; o < 3; o++) {
        const float scale = (o == 0) ? 0.125f : 1.0f;
        #pragma unroll
        for (int nt = 0; nt < 8; nt++) {
            const int col = nt * 8 + 2 * tg;
            float v00 = (acc[o][nt][0] + sbias[o][col])     * scale;
            float v01 = (acc[o][nt][1] + sbias[o][col + 1]) * scale;
            float v10 = (acc[o][nt][2] + sbias[o][col])     * scale;
            float v11 = (acc[o][nt][3] + sbias[o][col + 1]) * scale;
            if (o == 2) {
                *(float2*)(g_V + (size_t)r0 * H_ + col)       = make_float2(v00, v01);
                *(float2*)(g_V + (size_t)(r0 + 8) * H_ + col) = make_float2(v10, v11);
            } else {
                uint32_t* gh = (o == 0) ? g_Qh : g_Kh;
                uint32_t* gl = (o == 0) ? g_Ql : g_Kl;
                const int pi = nt * 4 + tg;
                uint32_t h0 = packbf(v00, v01);
                uint32_t h1 = packbf(v10, v11);
                gh[(size_t)r0 * 32 + pi]       = h0;
                gh[(size_t)(r0 + 8) * 32 + pi] = h1;
                gl[(size_t)r0 * 32 + pi]       = packbf(v00 - bflo(h0), v01 - bfhi(h0));
                gl[(size_t)(r0 + 8) * 32 + pi] = packbf(v10 - bflo(h1), v11 - bfhi(h1));
            }
        }
    }
}

// ---------------------------------------------------------------------------
// Kernel 2: split-KV causal flash attention via mma.sync bf16 (3-term split).
// grid (144, 8) LPT-decoded as in R3; block 128 = 4 warps x 16 q-rows.
// K tile cp.async'd (stride 36: conflict-free frag LDS); V tile converted +
// transposed + split into smem (stride 41: conflict-free STS).  Register-level
// online softmax on C fragments; P repacked in-register to A fragments.
// ---------------------------------------------------------------------------
#define KSTR 36
#define VSTR 41

__global__ __launch_bounds__(128) void attn_split_kernel()
{
    __shared__ __align__(16) uint32_t kh[64 * KSTR];
    __shared__ __align__(16) uint32_t kl[64 * KSTR];
    __shared__ uint32_t vth[64 * VSTR];
    __shared__ uint32_t vtl[64 * VSTR];

    const int bxr = 143 - (int)blockIdx.x;   // heavy first
    const int b   = blockIdx.y;

    int g = 0;
    #pragma unroll
    for (int h = 1; h < 8; h++)
        if (bxr >= 2 * h * (h + 1)) g = h;
    const int rem = bxr - 2 * g * (g + 1);
    const int qi  = rem / (g + 1);
    const int s   = rem - qi * (g + 1);
    const int t   = 4 * g + qi;              // q-block 0..31

    const int tid  = threadIdx.x;
    const int w    = tid >> 5;
    const int lane = tid & 31;
    const int gid  = lane >> 2;
    const int tg   = lane & 3;
    const int r0   = t * 64 + w * 16 + gid;  // q row (in-batch), second row r0+8

    // Q A-fragments (hi/lo), loaded once
    uint32_t qh[4][4], ql[4][4];
    {
        const uint32_t* qhp = g_Qh + ((size_t)b * T_ + r0) * 32;
        const uint32_t* qlp = g_Ql + ((size_t)b * T_ + r0) * 32;
        #pragma unroll
        for (int kk = 0; kk < 4; kk++) {
            qh[kk][0] = qhp[kk * 8 + tg];
            qh[kk][1] = qhp[8 * 32 + kk * 8 + tg];
            qh[kk][2] = qhp[kk * 8 + tg + 4];
            qh[kk][3] = qhp[8 * 32 + kk * 8 + tg + 4];
            ql[kk][0] = qlp[kk * 8 + tg];
            ql[kk][1] = qlp[8 * 32 + kk * 8 + tg];
            ql[kk][2] = qlp[kk * 8 + tg + 4];
            ql[kk][3] = qlp[8 * 32 + kk * 8 + tg + 4];
        }
    }

    float o[8][4];
    #pragma unroll
    for (int nt = 0; nt < 8; nt++)
        #pragma unroll
        for (int i = 0; i < 4; i++) o[nt][i] = 0.0f;
    float m0v = -1e30f, m1v = -1e30f, l0 = 0.0f, l1 = 0.0f;

    const uint32_t khb = smem_u32(kh), klb = smem_u32(kl);

    const int t0 = s * 4;
    const int t1 = min(s * 4 + 4, t + 1);

    for (int tt = t0; tt < t1; tt++) {
        const size_t krow = (size_t)b * T_ + tt * 64;
        // K hi/lo tiles via cp.async
        #pragma unroll
        for (int i = 0; i < 4; i++) {
            int c = i * 128 + tid;
            int row = c >> 3, gq = c & 7;
            cp_async16(khb + (row * KSTR + gq * 4) * 4, g_Kh + (krow + row) * 32 + gq * 4);
            cp_async16(klb + (row * KSTR + gq * 4) * 4, g_Kl + (krow + row) * 32 + gq * 4);
        }
        CP_COMMIT();

        // V tile: fp32 -> bf16 hi/lo, transposed [dim][keypair]
        {
            const float* Vt = g_V + krow * H_;
            #pragma unroll
            for (int i = 0; i < 16; i++) {
                int id = i * 128 + tid;
                int d = id & 63, kp = id >> 6;
                float v0 = Vt[(size_t)(2 * kp) * H_ + d];
                float v1 = Vt[(size_t)(2 * kp + 1) * H_ + d];
                uint32_t hp = packbf(v0, v1);
                vth[d * VSTR + kp] = hp;
                vtl[d * VSTR + kp] = packbf(v0 - bflo(hp), v1 - bfhi(hp));
            }
        }
        CP_WAIT0();
        __syncthreads();

        // ---- S = Q K^T (3-term) ----
        float st[8][4];
        #pragma unroll
        for (int nt = 0; nt < 8; nt++)
            #pragma unroll
            for (int i = 0; i < 4; i++) st[nt][i] = 0.0f;

        #pragma unroll
        for (int kk = 0; kk < 4; kk++) {
            #pragma unroll
            for (int nt = 0; nt < 8; nt++) {
                const uint32_t base = (uint32_t)(nt * 8 + gid) * KSTR + kk * 8 + tg;
                uint32_t bh0 = kh[base], bh1 = kh[base + 4];
                uint32_t bl0 = kl[base], bl1 = kl[base + 4];
                mma_bf16(st[nt], qh[kk][0], qh[kk][1], qh[kk][2], qh[kk][3], bh0, bh1);
                mma_bf16(st[nt], qh[kk][0], qh[kk][1], qh[kk][2], qh[kk][3], bl0, bl1);
                mma_bf16(st[nt], ql[kk][0], ql[kk][1], ql[kk][2], ql[kk][3], bh0, bh1);
            }
        }

        // causal mask (diagonal tile only)
        if (tt == t) {
            #pragma unroll
            for (int nt = 0; nt < 8; nt++) {
                int c0 = tt * 64 + nt * 8 + 2 * tg;
                if (c0     > r0)     st[nt][0] = -1e30f;
                if (c0 + 1 > r0)     st[nt][1] = -1e30f;
                if (c0     > r0 + 8) st[nt][2] = -1e30f;
                if (c0 + 1 > r0 + 8) st[nt][3] = -1e30f;
            }
        }

        // ---- online softmax on fragments ----
        float mn0 = m0v, mn1 = m1v;
        #pragma unroll
        for (int nt = 0; nt < 8; nt++) {
            mn0 = fmaxf(mn0, fmaxf(st[nt][0], st[nt][1]));
            mn1 = fmaxf(mn1, fmaxf(st[nt][2], st[nt][3]));
        }
        mn0 = fmaxf(mn0, __shfl_xor_sync(0xffffffffu, mn0, 1));
        mn0 = fmaxf(mn0, __shfl_xor_sync(0xffffffffu, mn0, 2));
        mn1 = fmaxf(mn1, __shfl_xor_sync(0xffffffffu, mn1, 1));
        mn1 = fmaxf(mn1, __shfl_xor_sync(0xffffffffu, mn1, 2));
        const float a0 = __expf(m0v - mn0);
        const float a1 = __expf(m1v - mn1);
        m0v = mn0; m1v = mn1;
        float rs0 = 0.0f, rs1 = 0.0f;
        #pragma unroll
        for (int nt = 0; nt < 8; nt++) {
            st[nt][0] = __expf(st[nt][0] - mn0);
            st[nt][1] = __expf(st[nt][1] - mn0);
            st[nt][2] = __expf(st[nt][2] - mn1);
            st[nt][3] = __expf(st[nt][3] - mn1);
            rs0 += st[nt][0] + st[nt][1];
            rs1 += st[nt][2] + st[nt][3];
        }
        l0 = l0 * a0 + rs0;
        l1 = l1 * a1 + rs1;
        #pragma unroll
        for (int nt = 0; nt < 8; nt++) {
            o[nt][0] *= a0; o[nt][1] *= a0;
            o[nt][2] *= a1; o[nt][3] *= a1;
        }

        // ---- O += P V (3-term) ----
        #pragma unroll
        for (int kk = 0; kk < 4; kk++) {
            uint32_t ph[4], pl[4];
            ph[0] = packbf(st[2 * kk][0],     st[2 * kk][1]);
            ph[1] = packbf(st[2 * kk][2],     st[2 * kk][3]);
            ph[2] = packbf(st[2 * kk + 1][0], st[2 * kk + 1][1]);
            ph[3] = packbf(st[2 * kk + 1][2], st[2 * kk + 1][3]);
            pl[0] = packbf(st[2 * kk][0]     - bflo(ph[0]), st[2 * kk][1]     - bfhi(ph[0]));
            pl[1] = packbf(st[2 * kk][2]     - bflo(ph[1]), st[2 * kk][3]     - bfhi(ph[1]));
            pl[2] = packbf(st[2 * kk + 1][0] - bflo(ph[2]), st[2 * kk + 1][1] - bfhi(ph[2]));
            pl[3] = packbf(st[2 * kk + 1][2] - bflo(ph[3]), st[2 * kk + 1][3] - bfhi(ph[3]));
            #pragma unroll
            for (int nd = 0; nd < 8; nd++) {
                const uint32_t base = (uint32_t)(nd * 8 + gid) * VSTR + kk * 8 + tg;
                uint32_t vh0 = vth[base], vh1 = vth[base + 4];
                uint32_t vl0 = vtl[base], vl1 = vtl[base + 4];
                mma_bf16(o[nd], ph[0], ph[1], ph[2], ph[3], vh0, vh1);
                mma_bf16(o[nd], pl[0], pl[1], pl[2], pl[3], vh0, vh1);
                mma_bf16(o[nd], ph[0], ph[1], ph[2], ph[3], vl0, vl1);
            }
        }
        __syncthreads();
    }

    // full-row l (quartet reduce)
    l0 += __shfl_xor_sync(0xffffffffu, l0, 1);
    l0 += __shfl_xor_sync(0xffffffffu, l0, 2);
    l1 += __shfl_xor_sync(0xffffffffu, l1, 1);
    l1 += __shfl_xor_sync(0xffffffffu, l1, 2);

    // write unnormalized partials
    const int rr = w * 16 + gid;
    float* op0 = &g_Op[b][t][s][rr][0];
    float* op1 = &g_Op[b][t][s][rr + 8][0];
    #pragma unroll
    for (int nt = 0; nt < 8; nt++) {
        const int col = nt * 8 + 2 * tg;
        *(float2*)(op0 + col) = make_float2(o[nt][0], o[nt][1]);
        *(float2*)(op1 + col) = make_float2(o[nt][2], o[nt][3]);
    }
    if (tg == 0) {
        g_Ml[b][t][s][rr][0]     = m0v;
        g_Ml[b][t][s][rr][1]     = l0;
        g_Ml[b][t][s][rr + 8][0] = m1v;
        g_Ml[b][t][s][rr + 8][1] = l1;
    }
}

// ---------------------------------------------------------------------------
// Kernel 3: combine split partials.  (unchanged)
// ---------------------------------------------------------------------------
__global__ __launch_bounds__(256) void attn_combine_kernel(float* __restrict__ out)
{
    const int t   = blockIdx.x;
    const int b   = blockIdx.y;
    const int tid = threadIdx.x;
    const int r   = tid >> 2;
    const int q4  = tid & 3;
    const int dbase = q4 * 16;
    const int ns  = t / 4 + 1;

    float mv[8], lv[8], wv[8];
    float M = -1e30f;
    for (int i = 0; i < ns; i++) {
        mv[i] = g_Ml[b][t][i][r][0];
        lv[i] = g_Ml[b][t][i][r][1];
        M = fmaxf(M, mv[i]);
    }
    float L = 0.0f;
    for (int i = 0; i < ns; i++) {
        wv[i] = __expf(mv[i] - M);
        L += wv[i] * lv[i];
    }
    const float invL = 1.0f / L;

    float acc[16];
    #pragma unroll
    for (int d = 0; d < 16; d++) acc[d] = 0.0f;

    for (int i = 0; i < ns; i++) {
        const float* op = &g_Op[b][t][i][r][dbase];
        const float wi = wv[i];
        #pragma unroll
        for (int d4 = 0; d4 < 4; d4++) {
            float4 v = *(const float4*)(op + d4 * 4);
            acc[d4 * 4 + 0] += wi * v.x;
            acc[d4 * 4 + 1] += wi * v.y;
            acc[d4 * 4 + 2] += wi * v.z;
            acc[d4 * 4 + 3] += wi * v.w;
        }
    }

    float* orow = out + ((size_t)b * T_ + t * 64 + r) * H_ + dbase;
    #pragma unroll
    for (int d4 = 0; d4 < 4; d4++) {
        float4 v;
        v.x = acc[d4 * 4 + 0] * invL;
        v.y = acc[d4 * 4 + 1] * invL;
        v.z = acc[d4 * 4 + 2] * invL;
        v.w = acc[d4 * 4 + 3] * invL;
        *(float4*)(orow + d4 * 4) = v;
    }
}

// ---------------------------------------------------------------------------
extern "C" void kernel_launch(void* const* d_in, const int* in_sizes, int n_in,
                              void* d_out, int out_size)
{
    const float* x  = (const float*)d_in[0];
    const float* Wq = (const float*)d_in[1];
    const float* bq = (const float*)d_in[2];
    const float* Wk = (const float*)d_in[3];
    const float* bk = (const float*)d_in[4];
    const float* Wv = (const float*)d_in[5];
    const float* bv = (const float*)d_in[6];
    float* out = (float*)d_out;

    cudaFuncSetAttribute(qkv_mma_kernel,
                         cudaFuncAttributeMaxDynamicSharedMemorySize, SMEM_DYN);

    wsplit_kernel<<<384, 256>>>(Wq, Wk, Wv);
    qkv_mma_kernel<<<128, 256, SMEM_DYN>>>(x, bq, bk, bv);
    attn_split_kernel<<<dim3(144, B_), 128>>>();
    attn_combine_kernel<<<dim3(32, B_), 256>>>(out);
}